// round 15
// baseline (speedup 1.0000x reference)
#include <cuda_runtime.h>
#include <cuda_fp16.h>
#include <math.h>
#include <stdint.h>

#define S_LEN  4096
#define BATCH  2
#define NH     8
#define HD     32
#define EDIM   256
#define WIN    64

#define KTOT   256
#define CH     64
#define NCHUNK (KTOT / CH)

typedef unsigned long long ull;

// ---- scratch (__device__ globals; no allocation allowed) ----
__device__ __half g_Qh[BATCH * NH * S_LEN * HD];   // fp16, scaled LOG2E/sqrt(32)
__device__ __half g_Kh[BATCH * NH * S_LEN * HD];
__device__ __half g_Vh[BATCH * NH * S_LEN * HD];
__device__ __half g_Os  [BATCH * S_LEN * KTOT];    // attn out fp16
__device__ __half g_Win2 [3 * EDIM * KTOT];        // in_proj_w fp16
__device__ __half g_Wout2[EDIM * KTOT];            // out_w fp16

// ============================ helpers ============================
__device__ __forceinline__ uint32_t smem_u32(const void* p) {
    uint32_t a;
    asm("{ .reg .u64 t; cvta.to.shared.u64 t, %1; cvt.u32.u64 %0, t; }" : "=r"(a) : "l"(p));
    return a;
}
__device__ __forceinline__ uint32_t sw128(uint32_t off) {
    return off ^ ((off >> 3) & 0x70);
}
__device__ __forceinline__ void ldmx4(uint32_t& r0, uint32_t& r1, uint32_t& r2, uint32_t& r3,
                                      uint32_t addr) {
    asm volatile("ldmatrix.sync.aligned.m8n8.x4.shared.b16 {%0,%1,%2,%3}, [%4];"
                 : "=r"(r0), "=r"(r1), "=r"(r2), "=r"(r3) : "r"(addr));
}
__device__ __forceinline__ void ldmx4t(uint32_t& r0, uint32_t& r1, uint32_t& r2, uint32_t& r3,
                                       uint32_t addr) {
    asm volatile("ldmatrix.sync.aligned.m8n8.x4.trans.shared.b16 {%0,%1,%2,%3}, [%4];"
                 : "=r"(r0), "=r"(r1), "=r"(r2), "=r"(r3) : "r"(addr));
}
__device__ __forceinline__ void mma16816h(float* c, const uint32_t* a, const uint32_t* b) {
    asm volatile(
        "mma.sync.aligned.m16n8k16.row.col.f32.f16.f16.f32 "
        "{%0,%1,%2,%3}, {%4,%5,%6,%7}, {%8,%9}, {%0,%1,%2,%3};"
        : "+f"(c[0]), "+f"(c[1]), "+f"(c[2]), "+f"(c[3])
        : "r"(a[0]), "r"(a[1]), "r"(a[2]), "r"(a[3]), "r"(b[0]), "r"(b[1]));
}
__device__ __forceinline__ float ex2(float x) {
    float y; asm("ex2.approx.ftz.f32 %0, %1;" : "=f"(y) : "f"(x)); return y;
}
// returns {lo = f16(b), hi = f16(a)}  (lo at lower address)
__device__ __forceinline__ uint32_t cvt2h(float a, float b) {
    uint32_t r; asm("cvt.rn.f16x2.f32 %0, %1, %2;" : "=r"(r) : "f"(a), "f"(b)); return r;
}

// ============================ weight conversion (tiny) ============================
#define NW2Q (3 * EDIM * EDIM / 4)   // 49152 float4s
#define NW3Q (EDIM * EDIM / 4)       // 16384

__global__ __launch_bounds__(256) void conv_w(const float* __restrict__ w1,
                                              const float* __restrict__ w2) {
    int i = blockIdx.x * 256 + threadIdx.x;
    const float4* src;
    __half* dst;
    int off;
    if (i < NW2Q) { src = (const float4*)w1; dst = g_Win2;  off = i; }
    else          { src = (const float4*)w2; dst = g_Wout2; off = i - NW2Q; }
    float4 v = src[off];
    __half2 a = __floats2half2_rn(v.x, v.y);
    __half2 b = __floats2half2_rn(v.z, v.w);
    uint2 u;
    u.x = *reinterpret_cast<uint32_t*>(&a);
    u.y = *reinterpret_cast<uint32_t*>(&b);
    *reinterpret_cast<uint2*>(dst + (size_t)off * 4) = u;
}

// ============================ QKV GEMM (TM=64, fused fp32->fp16 A conversion) ============================
// B: 4-stage full-prefetch cp.async ring (4 x 16KB = 64KB).
// A: LDG fp32 from x -> cvt -> swizzled STS fp16, 2 x 8KB double buffer.
#define QKV_SMEM (4 * 16384 + 2 * 8192)   // 81920

__global__ __launch_bounds__(256, 2) void hgemm_qkv(
    const float* __restrict__ X, const __half* __restrict__ B,
    const float* __restrict__ bias)
{
    extern __shared__ __align__(16) unsigned char dsm[];
    __shared__ float sbias[128];
    const uint32_t sbase = smem_u32(dsm);          // B ring
    const uint32_t abase = sbase + 4 * 16384;      // A bufs

    const int tid = threadIdx.x, lane = tid & 31, wid = tid >> 5;
    const int warp_m = wid >> 2, warp_n = wid & 3;
    const int m0 = blockIdx.y * 64, n0 = blockIdx.x * 128;

    if (tid < 128) sbias[tid] = bias[n0 + tid];

    float acc[2][4][4];
#pragma unroll
    for (int i = 0; i < 2; i++)
#pragma unroll
        for (int j = 0; j < 4; j++)
#pragma unroll
            for (int e = 0; e < 4; e++) acc[i][j][e] = 0.f;

    // ---- B prefetch: all 4 chunks ----
    const int r_ld = tid >> 3, c16 = tid & 7;
    const char* gB0 = (const char*)(B + (size_t)n0 * KTOT) + (size_t)r_ld * (KTOT * 2) + c16 * 16;
#pragma unroll
    for (int ch = 0; ch < NCHUNK; ch++) {
        uint32_t dB = sbase + ch * 16384;
        const char* gb = gB0 + ch * 128;
#pragma unroll
        for (int i = 0; i < 4; i++) {
            uint32_t sw = sw128((r_ld + i * 32) * 128 + c16 * 16);
            asm volatile("cp.async.cg.shared.global [%0], [%1], 16;"
                         :: "r"(dB + sw), "l"(gb + (size_t)i * 32 * (KTOT * 2)));
        }
        asm volatile("cp.async.commit_group;" ::: "memory");
    }

    // ---- A path: fp32 LDG -> fp16 STS ----
    const int ar = tid >> 2;            // row 0..63
    const int afo = (tid & 3) * 16;     // float offset within row chunk (0..48)
    const float* xrow = X + (size_t)(m0 + ar) * EDIM + afo;

    float4 ra[4];
#define LDG_A(ch)                                                          \
    do {                                                                   \
        const float4* p = reinterpret_cast<const float4*>(xrow + (ch) * CH); \
        ra[0] = p[0]; ra[1] = p[1]; ra[2] = p[2]; ra[3] = p[3];            \
    } while (0)
#define STS_A(buf)                                                         \
    do {                                                                   \
        uint32_t d = abase + (buf) * 8192;                                 \
        uint4 u0, u1;                                                      \
        __half2 h0 = __floats2half2_rn(ra[0].x, ra[0].y);                  \
        __half2 h1 = __floats2half2_rn(ra[0].z, ra[0].w);                  \
        __half2 h2 = __floats2half2_rn(ra[1].x, ra[1].y);                  \
        __half2 h3 = __floats2half2_rn(ra[1].z, ra[1].w);                  \
        u0.x = *reinterpret_cast<uint32_t*>(&h0);                          \
        u0.y = *reinterpret_cast<uint32_t*>(&h1);                          \
        u0.z = *reinterpret_cast<uint32_t*>(&h2);                          \
        u0.w = *reinterpret_cast<uint32_t*>(&h3);                          \
        __half2 h4 = __floats2half2_rn(ra[2].x, ra[2].y);                  \
        __half2 h5 = __floats2half2_rn(ra[2].z, ra[2].w);                  \
        __half2 h6 = __floats2half2_rn(ra[3].x, ra[3].y);                  \
        __half2 h7 = __floats2half2_rn(ra[3].z, ra[3].w);                  \
        u1.x = *reinterpret_cast<uint32_t*>(&h4);                          \
        u1.y = *reinterpret_cast<uint32_t*>(&h5);                          \
        u1.z = *reinterpret_cast<uint32_t*>(&h6);                          \
        u1.w = *reinterpret_cast<uint32_t*>(&h7);                          \
        *reinterpret_cast<uint4*>(dsm + 4 * 16384 + (buf) * 8192           \
            + sw128(ar * 128 + afo * 2))      = u0;                        \
        *reinterpret_cast<uint4*>(dsm + 4 * 16384 + (buf) * 8192           \
            + sw128(ar * 128 + afo * 2 + 16)) = u1;                        \
    } while (0)

    LDG_A(0);
    STS_A(0);
    LDG_A(1);

    const int akb  = (lane >> 4) * 16;
    const int brow4 = warp_n * 32 + ((lane >> 4) << 3) + (lane & 7);
    const int bkb4  = ((lane >> 3) & 1) * 16;

#pragma unroll
    for (int ch = 0; ch < NCHUNK; ch++) {
        if (ch == 0)      asm volatile("cp.async.wait_group 3;" ::: "memory");
        else if (ch == 1) asm volatile("cp.async.wait_group 2;" ::: "memory");
        else if (ch == 2) asm volatile("cp.async.wait_group 1;" ::: "memory");
        else              asm volatile("cp.async.wait_group 0;" ::: "memory");
        __syncthreads();   // B(ch) + A sts(ch) visible; compute(ch-1) done (A buf reuse safe)

        if (ch + 1 < NCHUNK) {
            STS_A((ch + 1) & 1);
            if (ch + 2 < NCHUNK) LDG_A(ch + 2);
        }

        const uint32_t sA = abase + (ch & 1) * 8192;
        const uint32_t sB = sbase + ch * 16384;
#pragma unroll
        for (int k16 = 0; k16 < 4; k16++) {
            uint32_t a[2][4], b[4][2];
#pragma unroll
            for (int mt = 0; mt < 2; mt++) {
                uint32_t addr = sA + sw128((warp_m * 32 + mt * 16 + (lane & 15)) * 128
                                           + k16 * 32 + akb);
                ldmx4(a[mt][0], a[mt][1], a[mt][2], a[mt][3], addr);
            }
#pragma unroll
            for (int np = 0; np < 2; np++) {
                uint32_t addr = sB + sw128((brow4 + np * 16) * 128 + k16 * 32 + bkb4);
                ldmx4(b[2 * np][0], b[2 * np][1], b[2 * np + 1][0], b[2 * np + 1][1], addr);
            }
#pragma unroll
            for (int mt = 0; mt < 2; mt++)
#pragma unroll
                for (int nt = 0; nt < 4; nt++)
                    mma16816h(acc[mt][nt], a[mt], b[nt]);
        }
    }
#undef LDG_A
#undef STS_A

    // register-direct epilogue -> g_Qh/g_Kh/g_Vh (half2 writes)
    const int gid = lane >> 2, tig = lane & 3;
    const int b_idx = m0 >> 12;
    const int which = n0 >> 8;
    const float sc = (which == 0) ? 0.2550348772f : 1.0f;  // LOG2E/sqrt(32)
    __half* dst = (which == 0) ? g_Qh : (which == 1) ? g_Kh : g_Vh;

#pragma unroll
    for (int mt = 0; mt < 2; mt++) {
        int r0 = m0 + warp_m * 32 + mt * 16 + gid;
#pragma unroll
        for (int nt = 0; nt < 4; nt++) {
            int cin = warp_n * 32 + nt * 8 + 2 * tig;
            int f = n0 + cin;
            int hh = (f >> 5) & 7, d0 = f & 31;
            float bx = sbias[cin], by = sbias[cin + 1];
            float v00 = (acc[mt][nt][0] + bx) * sc;
            float v01 = (acc[mt][nt][1] + by) * sc;
            float v10 = (acc[mt][nt][2] + bx) * sc;
            float v11 = (acc[mt][nt][3] + by) * sc;
            int s0 = r0 & (S_LEN - 1);
            __half* base = dst + ((size_t)(b_idx * NH + hh) * S_LEN) * HD + d0;
            *reinterpret_cast<uint32_t*>(base + (size_t)s0 * HD)       = cvt2h(v01, v00);
            *reinterpret_cast<uint32_t*>(base + (size_t)(s0 + 8) * HD) = cvt2h(v11, v10);
        }
    }
}

// ============================ out-proj GEMM (TM=32, fp16 A, 4-stage prefetch) ============================
// B ring 4 x 16KB = 64KB; A ring 4 x 4KB = 16KB.
#define OUT_SMEM (4 * 16384 + 4 * 4096)   // 81920

__global__ __launch_bounds__(256, 2) void hgemm_out(
    const __half* __restrict__ A, const __half* __restrict__ B,
    const float* __restrict__ bias, float* __restrict__ C)
{
    extern __shared__ __align__(16) unsigned char dsm[];
    __shared__ float sbias[128];
    const uint32_t sbase = smem_u32(dsm);        // B ring
    const uint32_t abase = sbase + 4 * 16384;    // A ring

    const int tid = threadIdx.x, lane = tid & 31, wid = tid >> 5;   // wid = warp_n 0..7
    const int m0 = blockIdx.y * 32, n0 = blockIdx.x * 128;

    if (tid < 128) sbias[tid] = bias[n0 + tid];

    float acc[2][2][4];
#pragma unroll
    for (int i = 0; i < 2; i++)
#pragma unroll
        for (int j = 0; j < 2; j++)
#pragma unroll
            for (int e = 0; e < 4; e++) acc[i][j][e] = 0.f;

    const int r_ld = tid >> 3, c16 = tid & 7;    // B: row 0..31 (stride 32), col16 0..7
    const char* gA0 = (const char*)(A + (size_t)m0 * KTOT) + (size_t)r_ld * (KTOT * 2) + c16 * 16;
    const char* gB0 = (const char*)(B + (size_t)n0 * KTOT) + (size_t)r_ld * (KTOT * 2) + c16 * 16;

    // prefetch all 4 chunks: A (1 ld/thread) + B (4 ld/thread)
#pragma unroll
    for (int ch = 0; ch < NCHUNK; ch++) {
        uint32_t dA = abase + ch * 4096;
        uint32_t dB = sbase + ch * 16384;
        const char* ga = gA0 + ch * 128;
        const char* gb = gB0 + ch * 128;
        {
            uint32_t sw = sw128(r_ld * 128 + c16 * 16);
            asm volatile("cp.async.cg.shared.global [%0], [%1], 16;"
                         :: "r"(dA + sw), "l"(ga));
        }
#pragma unroll
        for (int i = 0; i < 4; i++) {
            uint32_t sw = sw128((r_ld + i * 32) * 128 + c16 * 16);
            asm volatile("cp.async.cg.shared.global [%0], [%1], 16;"
                         :: "r"(dB + sw), "l"(gb + (size_t)i * 32 * (KTOT * 2)));
        }
        asm volatile("cp.async.commit_group;" ::: "memory");
    }

    const int akb  = (lane >> 4) * 16;
    const int brow4 = wid * 16 + ((lane >> 4) << 3) + (lane & 7);
    const int bkb4  = ((lane >> 3) & 1) * 16;

#pragma unroll
    for (int ch = 0; ch < NCHUNK; ch++) {
        if (ch == 0)      asm volatile("cp.async.wait_group 3;" ::: "memory");
        else if (ch == 1) asm volatile("cp.async.wait_group 2;" ::: "memory");
        else if (ch == 2) asm volatile("cp.async.wait_group 1;" ::: "memory");
        else              asm volatile("cp.async.wait_group 0;" ::: "memory");
        __syncthreads();

        const uint32_t sA = abase + ch * 4096;
        const uint32_t sB = sbase + ch * 16384;
#pragma unroll
        for (int k16 = 0; k16 < 4; k16++) {
            uint32_t a[2][4], b[2][2];
#pragma unroll
            for (int mt = 0; mt < 2; mt++) {
                uint32_t addr = sA + sw128((mt * 16 + (lane & 15)) * 128 + k16 * 32 + akb);
                ldmx4(a[mt][0], a[mt][1], a[mt][2], a[mt][3], addr);
            }
            {
                uint32_t addr = sB + sw128(brow4 * 128 + k16 * 32 + bkb4);
                ldmx4(b[0][0], b[0][1], b[1][0], b[1][1], addr);
            }
#pragma unroll
            for (int mt = 0; mt < 2; mt++)
#pragma unroll
                for (int nt = 0; nt < 2; nt++)
                    mma16816h(acc[mt][nt], a[mt], b[nt]);
        }
    }

    // register-direct fp32 epilogue
    const int gid = lane >> 2, tig = lane & 3;
#pragma unroll
    for (int mt = 0; mt < 2; mt++) {
        int r0 = m0 + mt * 16 + gid;
#pragma unroll
        for (int nt = 0; nt < 2; nt++) {
            int cin = wid * 16 + nt * 8 + 2 * tig;
            float bx = sbias[cin], by = sbias[cin + 1];
            *reinterpret_cast<float2*>(C + (size_t)r0 * EDIM + n0 + cin) =
                make_float2(acc[mt][nt][0] + bx, acc[mt][nt][1] + by);
            *reinterpret_cast<float2*>(C + (size_t)(r0 + 8) * EDIM + n0 + cin) =
                make_float2(acc[mt][nt][2] + bx, acc[mt][nt][3] + by);
        }
    }
}

// ============================ banded attention (plain fp16 HMMA flash) ============================
#define RP 80
#define AT_SMEM (256 * RP + 256 * RP + 128 * RP)   // 51200

__global__ __launch_bounds__(256, 2) void attn_mma()
{
    extern __shared__ __align__(16) unsigned char asmem[];
    unsigned char* sK = asmem;
    unsigned char* sV = asmem + 256 * RP;
    unsigned char* sQ = asmem + 2 * 256 * RP;
    const uint32_t uK = smem_u32(sK), uV = smem_u32(sV), uQ = smem_u32(sQ);

    const int t = threadIdx.x, lane = t & 31, w = t >> 5;
    const int q0 = blockIdx.x * 128, h = blockIdx.y, b = blockIdx.z;
    const size_t bh = (size_t)(b * NH + h) * S_LEN;
    const char* Kg = (const char*)(g_Kh + bh * HD);
    const char* Vg = (const char*)(g_Vh + bh * HD);
    const char* Qg = (const char*)(g_Qh + bh * HD);

#pragma unroll
    for (int i = 0; i < 4; i++) {
        int idx = t + 256 * i, r = idx >> 2, c = idx & 3;
        int j = q0 - 64 + r; j = j < 0 ? 0 : (j > S_LEN - 1 ? S_LEN - 1 : j);
        asm volatile("cp.async.cg.shared.global [%0], [%1], 16;"
                     :: "r"(uK + r * RP + c * 16), "l"(Kg + (size_t)j * 64 + c * 16));
        asm volatile("cp.async.cg.shared.global [%0], [%1], 16;"
                     :: "r"(uV + r * RP + c * 16), "l"(Vg + (size_t)j * 64 + c * 16));
    }
#pragma unroll
    for (int i = 0; i < 2; i++) {
        int idx = t + 256 * i, r = idx >> 2, c = idx & 3;
        asm volatile("cp.async.cg.shared.global [%0], [%1], 16;"
                     :: "r"(uQ + r * RP + c * 16), "l"(Qg + (size_t)(q0 + r) * 64 + c * 16));
    }
    asm volatile("cp.async.commit_group;" ::: "memory");
    asm volatile("cp.async.wait_group 0;" ::: "memory");
    __syncthreads();

    uint32_t aQ[2][4];
    {
        uint32_t base = uQ + (16 * w + (lane & 15)) * RP + (lane >> 4) * 16;
#pragma unroll
        for (int ks = 0; ks < 2; ks++)
            ldmx4(aQ[ks][0], aQ[ks][1], aQ[ks][2], aQ[ks][3], base + ks * 32);
    }

    float S[18][4];
#pragma unroll
    for (int nt = 0; nt < 18; nt++)
#pragma unroll
        for (int e = 0; e < 4; e++) S[nt][e] = 0.f;
    {
        uint32_t kb4 = uK + (16 * w + ((lane >> 4) << 3) + (lane & 7)) * RP
                     + ((lane >> 3) & 1) * 16;
#pragma unroll
        for (int ntp = 0; ntp < 9; ntp++) {
            uint32_t ad = kb4 + ntp * 16 * RP;
            uint32_t k0[4], k1[4];
            ldmx4(k0[0], k0[1], k0[2], k0[3], ad);
            ldmx4(k1[0], k1[1], k1[2], k1[3], ad + 32);
            float* s0 = S[2 * ntp];
            float* s1 = S[2 * ntp + 1];
            mma16816h(s0, aQ[0], k0);   mma16816h(s1, aQ[0], k0 + 2);
            mma16816h(s0, aQ[1], k1);   mma16816h(s1, aQ[1], k1 + 2);
        }
    }

    const int gid = lane >> 2, tig = lane & 3;
    const int jwb = q0 - 64 + 16 * w;
    float l0s = 0.f, l1s = 0.f;
    uint32_t Ph[18][2];
#pragma unroll
    for (int nt = 0; nt < 18; nt++) {
        int c0 = 8 * nt + 2 * tig, c1 = c0 + 1;
        int jg0 = jwb + c0, jg1 = jg0 + 1;
        bool in0 = (jg0 >= 0) && (jg0 < S_LEN);
        bool in1 = (jg1 >= 0) && (jg1 < S_LEN);
        bool v00 = in0 && (c0 >= gid)     && (c0 <= gid + 128);
        bool v01 = in1 && (c1 >= gid)     && (c1 <= gid + 128);
        bool v10 = in0 && (c0 >= gid + 8) && (c0 <= gid + 136);
        bool v11 = in1 && (c1 >= gid + 8) && (c1 <= gid + 136);
        float e00 = v00 ? ex2(S[nt][0]) : 0.f;
        float e01 = v01 ? ex2(S[nt][1]) : 0.f;
        float e10 = v10 ? ex2(S[nt][2]) : 0.f;
        float e11 = v11 ? ex2(S[nt][3]) : 0.f;
        l0s += e00 + e01; l1s += e10 + e11;
        Ph[nt][0] = cvt2h(e01, e00);
        Ph[nt][1] = cvt2h(e11, e10);
    }

    float O[4][4];
#pragma unroll
    for (int nt = 0; nt < 4; nt++)
#pragma unroll
        for (int e = 0; e < 4; e++) O[nt][e] = 0.f;
    {
        uint32_t vb4 = uV + (16 * w + (lane & 15)) * RP + (lane >> 4) * 16;
#pragma unroll
        for (int kk = 0; kk < 9; kk++) {
            uint32_t aH[4] = {Ph[2 * kk][0], Ph[2 * kk][1], Ph[2 * kk + 1][0], Ph[2 * kk + 1][1]};
            uint32_t rad = vb4 + kk * 16 * RP;
            uint32_t v0[4], v1[4];
            ldmx4t(v0[0], v0[1], v0[2], v0[3], rad);
            ldmx4t(v1[0], v1[1], v1[2], v1[3], rad + 32);
            mma16816h(O[0], aH, v0);   mma16816h(O[1], aH, v0 + 2);
            mma16816h(O[2], aH, v1);   mma16816h(O[3], aH, v1 + 2);
        }
    }

    l0s += __shfl_xor_sync(0xffffffffu, l0s, 1);
    l0s += __shfl_xor_sync(0xffffffffu, l0s, 2);
    l1s += __shfl_xor_sync(0xffffffffu, l1s, 1);
    l1s += __shfl_xor_sync(0xffffffffu, l1s, 2);
    const float inv0 = 1.f / l0s, inv1 = 1.f / l1s;

    const int m0r = b * S_LEN + q0 + 16 * w + gid;
#pragma unroll
    for (int nt = 0; nt < 4; nt++) {
        int c = h * HD + 8 * nt + 2 * tig;
        *reinterpret_cast<uint32_t*>(g_Os + (size_t)m0r * KTOT + c) =
            cvt2h(O[nt][1] * inv0, O[nt][0] * inv0);
        *reinterpret_cast<uint32_t*>(g_Os + (size_t)(m0r + 8) * KTOT + c) =
            cvt2h(O[nt][3] * inv1, O[nt][2] * inv1);
    }
}

// ============================ launch ============================
extern "C" void kernel_launch(void* const* d_in, const int* in_sizes, int n_in,
                              void* d_out, int out_size)
{
    const float* x    = (const float*)d_in[0];   // [2,4096,256]
    const float* in_w = (const float*)d_in[1];   // [768,256]
    const float* in_b = (const float*)d_in[2];   // [768]
    const float* ow   = (const float*)d_in[3];   // [256,256]
    const float* ob   = (const float*)d_in[4];   // [256]
    float* out = (float*)d_out;                  // [2,4096,256]

    __half *Os, *Win2, *Wout2;
    cudaGetSymbolAddress((void**)&Os,    g_Os);
    cudaGetSymbolAddress((void**)&Win2,  g_Win2);
    cudaGetSymbolAddress((void**)&Wout2, g_Wout2);

    cudaFuncSetAttribute(hgemm_qkv, cudaFuncAttributeMaxDynamicSharedMemorySize, QKV_SMEM);
    cudaFuncSetAttribute(hgemm_out, cudaFuncAttributeMaxDynamicSharedMemorySize, OUT_SMEM);
    cudaFuncSetAttribute(attn_mma,  cudaFuncAttributeMaxDynamicSharedMemorySize, AT_SMEM);

    // 0) weight conversions only (x converts inside hgemm_qkv)
    conv_w<<<(NW2Q + NW3Q) / 256, 256>>>(in_w, ow);

    // 1) QKV projection (fp32 A fused conversion) -> g_Qh/g_Kh/g_Vh
    {
        dim3 grid(3 * EDIM / 128, BATCH * S_LEN / 64);   // (6, 128) = 768 CTAs
        hgemm_qkv<<<grid, 256, QKV_SMEM>>>(x, Win2, in_b);
    }

    // 2) banded flash attention -> g_Os
    {
        dim3 grid(S_LEN / 128, NH, BATCH);               // (32, 8, 2) = 512 CTAs
        attn_mma<<<grid, 256, AT_SMEM>>>();
    }

    // 3) output projection (TM=32) -> out
    {
        dim3 grid(EDIM / 128, BATCH * S_LEN / 32);       // (2, 256) = 512 CTAs
        hgemm_out<<<grid, 256, OUT_SMEM>>>(Os, Wout2, ob, out);
    }
}

// round 16
// speedup vs baseline: 1.1827x; 1.1827x over previous
#include <cuda_runtime.h>
#include <cuda_fp16.h>
#include <math.h>
#include <stdint.h>

#define S_LEN  4096
#define BATCH  2
#define NH     8
#define HD     32
#define EDIM   256
#define WIN    64

#define KTOT   256
#define CH     64
#define NCHUNK (KTOT / CH)
#define TM     64
#define TN     128

typedef unsigned long long ull;

// ---- scratch (__device__ globals; no allocation allowed) ----
__device__ __half g_Qh[BATCH * NH * S_LEN * HD];   // fp16, scaled LOG2E/sqrt(32)
__device__ __half g_Kh[BATCH * NH * S_LEN * HD];
__device__ __half g_Vh[BATCH * NH * S_LEN * HD];
__device__ __half g_Xs  [BATCH * S_LEN * KTOT];
__device__ __half g_Os  [BATCH * S_LEN * KTOT];
__device__ __half g_Win2 [3 * EDIM * KTOT];
__device__ __half g_Wout2[EDIM * KTOT];

// ============================ helpers ============================
__device__ __forceinline__ uint32_t smem_u32(const void* p) {
    uint32_t a;
    asm("{ .reg .u64 t; cvta.to.shared.u64 t, %1; cvt.u32.u64 %0, t; }" : "=r"(a) : "l"(p));
    return a;
}
__device__ __forceinline__ uint32_t sw128(uint32_t off) {
    return off ^ ((off >> 3) & 0x70);
}
__device__ __forceinline__ void ldmx4(uint32_t& r0, uint32_t& r1, uint32_t& r2, uint32_t& r3,
                                      uint32_t addr) {
    asm volatile("ldmatrix.sync.aligned.m8n8.x4.shared.b16 {%0,%1,%2,%3}, [%4];"
                 : "=r"(r0), "=r"(r1), "=r"(r2), "=r"(r3) : "r"(addr));
}
__device__ __forceinline__ void ldmx4t(uint32_t& r0, uint32_t& r1, uint32_t& r2, uint32_t& r3,
                                       uint32_t addr) {
    asm volatile("ldmatrix.sync.aligned.m8n8.x4.trans.shared.b16 {%0,%1,%2,%3}, [%4];"
                 : "=r"(r0), "=r"(r1), "=r"(r2), "=r"(r3) : "r"(addr));
}
__device__ __forceinline__ void mma16816h(float* c, const uint32_t* a, const uint32_t* b) {
    asm volatile(
        "mma.sync.aligned.m16n8k16.row.col.f32.f16.f16.f32 "
        "{%0,%1,%2,%3}, {%4,%5,%6,%7}, {%8,%9}, {%0,%1,%2,%3};"
        : "+f"(c[0]), "+f"(c[1]), "+f"(c[2]), "+f"(c[3])
        : "r"(a[0]), "r"(a[1]), "r"(a[2]), "r"(a[3]), "r"(b[0]), "r"(b[1]));
}
__device__ __forceinline__ float ex2(float x) {
    float y; asm("ex2.approx.ftz.f32 %0, %1;" : "=f"(y) : "f"(x)); return y;
}
// returns {lo = f16(b), hi = f16(a)}  (lo at lower address)
__device__ __forceinline__ uint32_t cvt2h(float a, float b) {
    uint32_t r; asm("cvt.rn.f16x2.f32 %0, %1, %2;" : "=r"(r) : "f"(a), "f"(b)); return r;
}

// ============================ fused conversion kernel ============================
#define N1Q (BATCH * S_LEN * EDIM / 4)   // 524288
#define N2Q (3 * EDIM * EDIM / 4)        // 49152
#define N3Q (EDIM * EDIM / 4)            // 16384

__global__ __launch_bounds__(256) void conv_all(const float* __restrict__ x,
                                                const float* __restrict__ w1,
                                                const float* __restrict__ w2) {
    int i = blockIdx.x * 256 + threadIdx.x;
    const float4* src;
    __half* dst;
    int off;
    if (i < N1Q)            { src = (const float4*)x;  dst = g_Xs;   off = i; }
    else if (i < N1Q + N2Q) { src = (const float4*)w1; dst = g_Win2; off = i - N1Q; }
    else                    { src = (const float4*)w2; dst = g_Wout2; off = i - N1Q - N2Q; }
    float4 v = src[off];
    __half2 a = __floats2half2_rn(v.x, v.y);
    __half2 b = __floats2half2_rn(v.z, v.w);
    uint2 u;
    u.x = *reinterpret_cast<uint32_t*>(&a);
    u.y = *reinterpret_cast<uint32_t*>(&b);
    *reinterpret_cast<uint2*>(dst + (size_t)off * 4) = u;
#if __CUDA_ARCH__ >= 900
    cudaTriggerProgrammaticLaunchCompletion();
#endif
}

// ============================ fp16 HMMA GEMM (64x128 tile, 4-stage full prefetch) ============================
// MODE 1: A,B both depend on conv -> griddepsync at top, per-chunk {A,B} groups.
// MODE 0: B (weights) independent of attn -> B groups pre-sync, A groups post-sync.
// Either way: 4 "per-chunk-completing" waits of wait_group (3-ch).
#define STAGE_BYTES 24576
#define GEMM_SMEM (4 * STAGE_BYTES)

template <int MODE>
__global__ __launch_bounds__(256, 2) void hgemm(
    const __half* __restrict__ A, const __half* __restrict__ B,
    const float* __restrict__ bias, float* __restrict__ C)
{
    extern __shared__ __align__(16) unsigned char dsm[];
    __shared__ float sbias[TN];
    const uint32_t sbase = smem_u32(dsm);

    const int tid = threadIdx.x, lane = tid & 31, wid = tid >> 5;
    const int warp_m = wid >> 2;          // 0..1 (32 rows each)
    const int warp_n = wid & 3;           // 0..3 (32 cols each)
    const int m0 = blockIdx.y * TM, n0 = blockIdx.x * TN;

    float acc[2][4][4];
#pragma unroll
    for (int i = 0; i < 2; i++)
#pragma unroll
        for (int j = 0; j < 4; j++)
#pragma unroll
            for (int e = 0; e < 4; e++) acc[i][j][e] = 0.f;

    const int r_ld = tid >> 3, c16 = tid & 7;   // row 0..31, 16B col 0..7
    const char* gA0 = (const char*)(A + (size_t)m0 * KTOT) + (size_t)r_ld * (KTOT * 2) + c16 * 16;
    const char* gB0 = (const char*)(B + (size_t)n0 * KTOT) + (size_t)r_ld * (KTOT * 2) + c16 * 16;

    const int akb  = (lane >> 4) * 16;
    const int brow4 = warp_n * 32 + ((lane >> 4) << 3) + (lane & 7);
    const int bkb4  = ((lane >> 3) & 1) * 16;

    if (MODE == 0) {
        // B prefetch (weights, ready long ago) BEFORE waiting on attention
#pragma unroll
        for (int ch = 0; ch < NCHUNK; ch++) {
            uint32_t dB = sbase + ch * STAGE_BYTES + 8192;
            const char* gb = gB0 + ch * 128;
#pragma unroll
            for (int i = 0; i < 4; i++) {
                uint32_t sw = sw128((r_ld + i * 32) * 128 + c16 * 16);
                asm volatile("cp.async.cg.shared.global [%0], [%1], 16;"
                             :: "r"(dB + sw), "l"(gb + (size_t)i * 32 * (KTOT * 2)));
            }
            asm volatile("cp.async.commit_group;" ::: "memory");
        }
#if __CUDA_ARCH__ >= 900
        cudaGridDependencySynchronize();
#endif
        if (tid < TN) sbias[tid] = bias[n0 + tid];
#pragma unroll
        for (int ch = 0; ch < NCHUNK; ch++) {
            uint32_t dA = sbase + ch * STAGE_BYTES;
            const char* ga = gA0 + ch * 128;
#pragma unroll
            for (int i = 0; i < 2; i++) {
                uint32_t sw = sw128((r_ld + i * 32) * 128 + c16 * 16);
                asm volatile("cp.async.cg.shared.global [%0], [%1], 16;"
                             :: "r"(dA + sw), "l"(ga + (size_t)i * 32 * (KTOT * 2)));
            }
            asm volatile("cp.async.commit_group;" ::: "memory");
        }
        // 8 groups: B0..B3, A0..A3. wait_group (3-ch) completes B0-3 + A0..Ach.
    } else {
#if __CUDA_ARCH__ >= 900
        cudaGridDependencySynchronize();
#endif
        if (tid < TN) sbias[tid] = bias[n0 + tid];
#pragma unroll
        for (int ch = 0; ch < NCHUNK; ch++) {
            uint32_t dA = sbase + ch * STAGE_BYTES;
            uint32_t dB = dA + 8192;
            const char* ga = gA0 + ch * 128;
            const char* gb = gB0 + ch * 128;
#pragma unroll
            for (int i = 0; i < 2; i++) {
                uint32_t sw = sw128((r_ld + i * 32) * 128 + c16 * 16);
                asm volatile("cp.async.cg.shared.global [%0], [%1], 16;"
                             :: "r"(dA + sw), "l"(ga + (size_t)i * 32 * (KTOT * 2)));
            }
#pragma unroll
            for (int i = 0; i < 4; i++) {
                uint32_t sw = sw128((r_ld + i * 32) * 128 + c16 * 16);
                asm volatile("cp.async.cg.shared.global [%0], [%1], 16;"
                             :: "r"(dB + sw), "l"(gb + (size_t)i * 32 * (KTOT * 2)));
            }
            asm volatile("cp.async.commit_group;" ::: "memory");
        }
    }

#pragma unroll
    for (int ch = 0; ch < NCHUNK; ch++) {
        if (ch == 0)      asm volatile("cp.async.wait_group 3;" ::: "memory");
        else if (ch == 1) asm volatile("cp.async.wait_group 2;" ::: "memory");
        else if (ch == 2) asm volatile("cp.async.wait_group 1;" ::: "memory");
        else              asm volatile("cp.async.wait_group 0;" ::: "memory");
        __syncthreads();

        const uint32_t sA = sbase + ch * STAGE_BYTES;
        const uint32_t sB = sA + 8192;
#pragma unroll
        for (int k16 = 0; k16 < 4; k16++) {
            uint32_t a[2][4], b[4][2];
#pragma unroll
            for (int mt = 0; mt < 2; mt++) {
                uint32_t addr = sA + sw128((warp_m * 32 + mt * 16 + (lane & 15)) * 128
                                           + k16 * 32 + akb);
                ldmx4(a[mt][0], a[mt][1], a[mt][2], a[mt][3], addr);
            }
#pragma unroll
            for (int np = 0; np < 2; np++) {
                uint32_t addr = sB + sw128((brow4 + np * 16) * 128 + k16 * 32 + bkb4);
                ldmx4(b[2 * np][0], b[2 * np][1], b[2 * np + 1][0], b[2 * np + 1][1], addr);
            }
#pragma unroll
            for (int mt = 0; mt < 2; mt++)
#pragma unroll
                for (int nt = 0; nt < 4; nt++)
                    mma16816h(acc[mt][nt], a[mt], b[nt]);
        }
    }

    // ============ register-direct epilogue ============
    const int gid = lane >> 2, tig = lane & 3;
    const int b_idx = m0 >> 12;
    const int which = n0 >> 8;
    const float sc = (MODE == 1 && which == 0) ? 0.2550348772f : 1.0f;  // LOG2E/sqrt(32)

    if (MODE == 1) {
        __half* dst = (which == 0) ? g_Qh : (which == 1) ? g_Kh : g_Vh;
#pragma unroll
        for (int mt = 0; mt < 2; mt++) {
            int r0 = m0 + warp_m * 32 + mt * 16 + gid;       // rows r0, r0+8
#pragma unroll
            for (int nt = 0; nt < 4; nt++) {
                int cin = warp_n * 32 + nt * 8 + 2 * tig;    // col within tile
                int f = n0 + cin;
                int hh = (f >> 5) & 7, d0 = f & 31;
                float bx = sbias[cin], by = sbias[cin + 1];
                float v00 = (acc[mt][nt][0] + bx) * sc;
                float v01 = (acc[mt][nt][1] + by) * sc;
                float v10 = (acc[mt][nt][2] + bx) * sc;
                float v11 = (acc[mt][nt][3] + by) * sc;
                int s0 = r0 & (S_LEN - 1);
                __half* base = dst + ((size_t)(b_idx * NH + hh) * S_LEN) * HD + d0;
                *reinterpret_cast<uint32_t*>(base + (size_t)s0 * HD)       = cvt2h(v01, v00);
                *reinterpret_cast<uint32_t*>(base + (size_t)(s0 + 8) * HD) = cvt2h(v11, v10);
            }
        }
    } else {
#pragma unroll
        for (int mt = 0; mt < 2; mt++) {
            int r0 = m0 + warp_m * 32 + mt * 16 + gid;
#pragma unroll
            for (int nt = 0; nt < 4; nt++) {
                int cin = warp_n * 32 + nt * 8 + 2 * tig;
                float bx = sbias[cin], by = sbias[cin + 1];
                *reinterpret_cast<float2*>(C + (size_t)r0 * EDIM + n0 + cin) =
                    make_float2(acc[mt][nt][0] + bx, acc[mt][nt][1] + by);
                *reinterpret_cast<float2*>(C + (size_t)(r0 + 8) * EDIM + n0 + cin) =
                    make_float2(acc[mt][nt][2] + bx, acc[mt][nt][3] + by);
            }
        }
    }
#if __CUDA_ARCH__ >= 900
    if (MODE == 1) cudaTriggerProgrammaticLaunchCompletion();
#endif
}

// ============================ banded attention (plain fp16 HMMA flash) ============================
#define RP 80
#define AT_SMEM (256 * RP + 256 * RP + 128 * RP)   // K + V + Q = 51200

__global__ __launch_bounds__(256, 2) void attn_mma()
{
    extern __shared__ __align__(16) unsigned char asmem[];
    unsigned char* sK = asmem;
    unsigned char* sV = asmem + 256 * RP;
    unsigned char* sQ = asmem + 2 * 256 * RP;
    const uint32_t uK = smem_u32(sK), uV = smem_u32(sV), uQ = smem_u32(sQ);

    const int t = threadIdx.x, lane = t & 31, w = t >> 5;
    const int q0 = blockIdx.x * 128, h = blockIdx.y, b = blockIdx.z;
    const size_t bh = (size_t)(b * NH + h) * S_LEN;
    const char* Kg = (const char*)(g_Kh + bh * HD);
    const char* Vg = (const char*)(g_Vh + bh * HD);
    const char* Qg = (const char*)(g_Qh + bh * HD);

#if __CUDA_ARCH__ >= 900
    cudaGridDependencySynchronize();   // all loads depend on QKV projection
#endif

#pragma unroll
    for (int i = 0; i < 4; i++) {
        int idx = t + 256 * i, r = idx >> 2, c = idx & 3;
        int j = q0 - 64 + r; j = j < 0 ? 0 : (j > S_LEN - 1 ? S_LEN - 1 : j);
        asm volatile("cp.async.cg.shared.global [%0], [%1], 16;"
                     :: "r"(uK + r * RP + c * 16), "l"(Kg + (size_t)j * 64 + c * 16));
        asm volatile("cp.async.cg.shared.global [%0], [%1], 16;"
                     :: "r"(uV + r * RP + c * 16), "l"(Vg + (size_t)j * 64 + c * 16));
    }
#pragma unroll
    for (int i = 0; i < 2; i++) {
        int idx = t + 256 * i, r = idx >> 2, c = idx & 3;
        asm volatile("cp.async.cg.shared.global [%0], [%1], 16;"
                     :: "r"(uQ + r * RP + c * 16), "l"(Qg + (size_t)(q0 + r) * 64 + c * 16));
    }
    asm volatile("cp.async.commit_group;" ::: "memory");
    asm volatile("cp.async.wait_group 0;" ::: "memory");
    __syncthreads();

    uint32_t aQ[2][4];
    {
        uint32_t base = uQ + (16 * w + (lane & 15)) * RP + (lane >> 4) * 16;
#pragma unroll
        for (int ks = 0; ks < 2; ks++)
            ldmx4(aQ[ks][0], aQ[ks][1], aQ[ks][2], aQ[ks][3], base + ks * 32);
    }

    float S[18][4];
#pragma unroll
    for (int nt = 0; nt < 18; nt++)
#pragma unroll
        for (int e = 0; e < 4; e++) S[nt][e] = 0.f;
    {
        uint32_t kb4 = uK + (16 * w + ((lane >> 4) << 3) + (lane & 7)) * RP
                     + ((lane >> 3) & 1) * 16;
#pragma unroll
        for (int ntp = 0; ntp < 9; ntp++) {
            uint32_t ad = kb4 + ntp * 16 * RP;
            uint32_t k0[4], k1[4];
            ldmx4(k0[0], k0[1], k0[2], k0[3], ad);
            ldmx4(k1[0], k1[1], k1[2], k1[3], ad + 32);
            float* s0 = S[2 * ntp];
            float* s1 = S[2 * ntp + 1];
            mma16816h(s0, aQ[0], k0);   mma16816h(s1, aQ[0], k0 + 2);
            mma16816h(s0, aQ[1], k1);   mma16816h(s1, aQ[1], k1 + 2);
        }
    }

    const int gid = lane >> 2, tig = lane & 3;
    const int jwb = q0 - 64 + 16 * w;
    float l0s = 0.f, l1s = 0.f;
    uint32_t Ph[18][2];
#pragma unroll
    for (int nt = 0; nt < 18; nt++) {
        int c0 = 8 * nt + 2 * tig, c1 = c0 + 1;
        int jg0 = jwb + c0, jg1 = jg0 + 1;
        bool in0 = (jg0 >= 0) && (jg0 < S_LEN);
        bool in1 = (jg1 >= 0) && (jg1 < S_LEN);
        bool v00 = in0 && (c0 >= gid)     && (c0 <= gid + 128);
        bool v01 = in1 && (c1 >= gid)     && (c1 <= gid + 128);
        bool v10 = in0 && (c0 >= gid + 8) && (c0 <= gid + 136);
        bool v11 = in1 && (c1 >= gid + 8) && (c1 <= gid + 136);
        float e00 = v00 ? ex2(S[nt][0]) : 0.f;
        float e01 = v01 ? ex2(S[nt][1]) : 0.f;
        float e10 = v10 ? ex2(S[nt][2]) : 0.f;
        float e11 = v11 ? ex2(S[nt][3]) : 0.f;
        l0s += e00 + e01; l1s += e10 + e11;
        Ph[nt][0] = cvt2h(e01, e00);
        Ph[nt][1] = cvt2h(e11, e10);
    }

    float O[4][4];
#pragma unroll
    for (int nt = 0; nt < 4; nt++)
#pragma unroll
        for (int e = 0; e < 4; e++) O[nt][e] = 0.f;
    {
        uint32_t vb4 = uV + (16 * w + (lane & 15)) * RP + (lane >> 4) * 16;
#pragma unroll
        for (int kk = 0; kk < 9; kk++) {
            uint32_t aH[4] = {Ph[2 * kk][0], Ph[2 * kk][1], Ph[2 * kk + 1][0], Ph[2 * kk + 1][1]};
            uint32_t rad = vb4 + kk * 16 * RP;
            uint32_t v0[4], v1[4];
            ldmx4t(v0[0], v0[1], v0[2], v0[3], rad);
            ldmx4t(v1[0], v1[1], v1[2], v1[3], rad + 32);
            mma16816h(O[0], aH, v0);   mma16816h(O[1], aH, v0 + 2);
            mma16816h(O[2], aH, v1);   mma16816h(O[3], aH, v1 + 2);
        }
    }

    l0s += __shfl_xor_sync(0xffffffffu, l0s, 1);
    l0s += __shfl_xor_sync(0xffffffffu, l0s, 2);
    l1s += __shfl_xor_sync(0xffffffffu, l1s, 1);
    l1s += __shfl_xor_sync(0xffffffffu, l1s, 2);
    const float inv0 = 1.f / l0s, inv1 = 1.f / l1s;

    // register-direct fp16 writes into g_Os
    const int m0r = b * S_LEN + q0 + 16 * w + gid;     // rows m0r, m0r+8
#pragma unroll
    for (int nt = 0; nt < 4; nt++) {
        int c = h * HD + 8 * nt + 2 * tig;
        *reinterpret_cast<uint32_t*>(g_Os + (size_t)m0r * KTOT + c) =
            cvt2h(O[nt][1] * inv0, O[nt][0] * inv0);
        *reinterpret_cast<uint32_t*>(g_Os + (size_t)(m0r + 8) * KTOT + c) =
            cvt2h(O[nt][3] * inv1, O[nt][2] * inv1);
    }
#if __CUDA_ARCH__ >= 900
    cudaTriggerProgrammaticLaunchCompletion();
#endif
}

// ============================ launch ============================
extern "C" void kernel_launch(void* const* d_in, const int* in_sizes, int n_in,
                              void* d_out, int out_size)
{
    const float* x    = (const float*)d_in[0];   // [2,4096,256]
    const float* in_w = (const float*)d_in[1];   // [768,256]
    const float* in_b = (const float*)d_in[2];   // [768]
    const float* ow   = (const float*)d_in[3];   // [256,256]
    const float* ob   = (const float*)d_in[4];   // [256]
    float* out = (float*)d_out;                  // [2,4096,256]

    __half *Xs, *Os, *Win2, *Wout2;
    cudaGetSymbolAddress((void**)&Xs,    g_Xs);
    cudaGetSymbolAddress((void**)&Os,    g_Os);
    cudaGetSymbolAddress((void**)&Win2,  g_Win2);
    cudaGetSymbolAddress((void**)&Wout2, g_Wout2);

    cudaFuncSetAttribute(hgemm<1>, cudaFuncAttributeMaxDynamicSharedMemorySize, GEMM_SMEM);
    cudaFuncSetAttribute(hgemm<0>, cudaFuncAttributeMaxDynamicSharedMemorySize, GEMM_SMEM);
    cudaFuncSetAttribute(attn_mma, cudaFuncAttributeMaxDynamicSharedMemorySize, AT_SMEM);

    // 0) fused fp16 conversions
    conv_all<<<(N1Q + N2Q + N3Q) / 256, 256>>>(x, in_w, ow);

    // PDL launch config (programmatic serialization with the preceding kernel)
    cudaLaunchAttribute pdl[1];
    pdl[0].id = cudaLaunchAttributeProgrammaticStreamSerialization;
    pdl[0].val.programmaticStreamSerializationAllowed = 1;

    // 1) QKV projection -> g_Qh/g_Kh/g_Vh
    {
        cudaLaunchConfig_t cfg = {};
        cfg.gridDim = dim3(3 * EDIM / TN, BATCH * S_LEN / TM, 1);   // (6, 128)
        cfg.blockDim = dim3(256, 1, 1);
        cfg.dynamicSmemBytes = GEMM_SMEM;
        cfg.attrs = pdl; cfg.numAttrs = 1;
        cudaLaunchKernelEx(&cfg, hgemm<1>, (const __half*)Xs, (const __half*)Win2,
                           in_b, (float*)nullptr);
    }

    // 2) banded flash attention -> g_Os
    {
        cudaLaunchConfig_t cfg = {};
        cfg.gridDim = dim3(S_LEN / 128, NH, BATCH);                 // (32, 8, 2)
        cfg.blockDim = dim3(256, 1, 1);
        cfg.dynamicSmemBytes = AT_SMEM;
        cfg.attrs = pdl; cfg.numAttrs = 1;
        cudaLaunchKernelEx(&cfg, attn_mma);
    }

    // 3) output projection -> out (B prefetch overlaps attention tail)
    {
        cudaLaunchConfig_t cfg = {};
        cfg.gridDim = dim3(EDIM / TN, BATCH * S_LEN / TM, 1);       // (2, 128)
        cfg.blockDim = dim3(256, 1, 1);
        cfg.dynamicSmemBytes = GEMM_SMEM;
        cfg.attrs = pdl; cfg.numAttrs = 1;
        cudaLaunchKernelEx(&cfg, hgemm<0>, (const __half*)Os, (const __half*)Wout2,
                           ob, out);
    }
}